// round 14
// baseline (speedup 1.0000x reference)
#include <cuda_runtime.h>
#include <cstdint>

// Problem constants
#define DEPTH 2
#define NEXP  16
#define HDIM  1024
#define NTOK  8192
#define CAP   4096

// GEMM tile config (mma.sync tf32x3, pre-split hi/lo interleaved)
#define BM 128
#define BN 128
#define KC 16            // K floats per chunk
#define NTHREADS 256
#define SPAD 20          // smem row stride in float2 (160B, conflict-free for LDS.64)

// ---------------------------------------------------------------------------
// Device-global scratch
// ---------------------------------------------------------------------------
__device__ float  g_act[(size_t)NTOK * HDIM];
__device__ float  g_pair[(size_t)NTOK * 2 * HDIM];
__device__ int    g_cnt[NEXP];
__device__ int    g_tok[NEXP * CAP];
__device__ float  g_wt[NEXP * CAP];
__device__ float2 g_ew2[(size_t)DEPTH * NEXP * HDIM * HDIM];   // (hi,lo) interleaved, 268 MB
__device__ float2 g_a2[(size_t)NTOK * HDIM];                   // (hi,lo) interleaved, 67 MB

// ---------------------------------------------------------------------------
// PTX helpers
// ---------------------------------------------------------------------------
__device__ __forceinline__ float f2tf_hi(float x) {
    uint32_t u;
    asm("cvt.rna.tf32.f32 %0, %1;" : "=r"(u) : "f"(x));
    return __uint_as_float(u);
}

__device__ __forceinline__ void mma4(float* d,
                                     uint32_t a0, uint32_t a1, uint32_t a2, uint32_t a3,
                                     uint32_t b0, uint32_t b1) {
    asm volatile(
        "mma.sync.aligned.m16n8k8.row.col.f32.tf32.tf32.f32 "
        "{%0,%1,%2,%3}, {%4,%5,%6,%7}, {%8,%9}, {%0,%1,%2,%3};"
        : "+f"(d[0]), "+f"(d[1]), "+f"(d[2]), "+f"(d[3])
        : "r"(a0), "r"(a1), "r"(a2), "r"(a3), "r"(b0), "r"(b1));
}

__device__ __forceinline__ void cp16(uint32_t smem_dst, const void* gsrc) {
    asm volatile("cp.async.cg.shared.global [%0], [%1], 16;" :: "r"(smem_dst), "l"(gsrc));
}
__device__ __forceinline__ void cp_commit() { asm volatile("cp.async.commit_group;"); }
__device__ __forceinline__ void cp_wait1()  { asm volatile("cp.async.wait_group 1;"); }
__device__ __forceinline__ void cp_wait0()  { asm volatile("cp.async.wait_group 0;"); }

__device__ __forceinline__ uint32_t smem_u32(const void* p) {
    uint32_t a;
    asm("{ .reg .u64 t; cvta.to.shared.u64 t, %1; cvt.u32.u64 %0, t; }" : "=r"(a) : "l"(p));
    return a;
}

// ---------------------------------------------------------------------------
// Kernel 0: reset per-expert counters
// ---------------------------------------------------------------------------
__global__ void reset_kernel() {
    if (threadIdx.x < NEXP) g_cnt[threadIdx.x] = 0;
}

// ---------------------------------------------------------------------------
// Split kernels: v -> interleaved (hi = rna.tf32(v), lo = v - hi)
// Each thread handles 4 elements (one float4 in, two float4 out).
// ---------------------------------------------------------------------------
__global__ __launch_bounds__(256) void split_ew_kernel(const float* __restrict__ ew) {
    size_t i = (size_t)blockIdx.x * 256 + threadIdx.x;   // over D*E*H*H / 4
    float4 v = reinterpret_cast<const float4*>(ew)[i];
    float hx = f2tf_hi(v.x), hy = f2tf_hi(v.y), hz = f2tf_hi(v.z), hw = f2tf_hi(v.w);
    float4 o0 = make_float4(hx, v.x - hx, hy, v.y - hy);
    float4 o1 = make_float4(hz, v.z - hz, hw, v.w - hw);
    float4* dst = reinterpret_cast<float4*>(g_ew2);
    dst[2 * i]     = o0;
    dst[2 * i + 1] = o1;
}

__global__ __launch_bounds__(256) void split_act_kernel(int layer, const float* __restrict__ Xext) {
    const float* x = (layer == 0) ? Xext : g_act;
    size_t i = (size_t)blockIdx.x * 256 + threadIdx.x;   // over NTOK*HDIM / 4
    float4 v = reinterpret_cast<const float4*>(x)[i];
    float hx = f2tf_hi(v.x), hy = f2tf_hi(v.y), hz = f2tf_hi(v.z), hw = f2tf_hi(v.w);
    float4 o0 = make_float4(hx, v.x - hx, hy, v.y - hy);
    float4 o1 = make_float4(hz, v.z - hz, hw, v.w - hw);
    float4* dst = reinterpret_cast<float4*>(g_a2);
    dst[2 * i]     = o0;
    dst[2 * i + 1] = o1;
}

// ---------------------------------------------------------------------------
// Kernel 1: gating (unchanged from R10 passing version)
// ---------------------------------------------------------------------------
__global__ __launch_bounds__(256) void gate_kernel(
    int layer, const float* __restrict__ Xext,
    const float* __restrict__ gw, const float* __restrict__ gb)
{
    const float* x = (layer == 0) ? Xext : g_act;
    __shared__ float4 sx4[8 * (HDIM / 4)];

    int tid = threadIdx.x;
    const float4* x4 = reinterpret_cast<const float4*>(x);
    #pragma unroll
    for (int i = tid; i < 8 * (HDIM / 4); i += 256)
        sx4[i] = x4[(size_t)blockIdx.x * (8 * HDIM / 4) + i];
    __syncthreads();

    int wid = tid >> 5, lane = tid & 31;
    int b = blockIdx.x * 8 + wid;

    const float4* gw4 = reinterpret_cast<const float4*>(gw);
    float G[NEXP];
    #pragma unroll
    for (int e = 0; e < NEXP; e++) {
        float acc = 0.f;
        #pragma unroll
        for (int j = 0; j < 8; j++) {
            float4 xv = sx4[wid * 256 + j * 32 + lane];
            float4 wv = gw4[e * 256 + j * 32 + lane];
            acc += xv.x * wv.x + xv.y * wv.y + xv.z * wv.z + xv.w * wv.w;
        }
        #pragma unroll
        for (int off = 16; off; off >>= 1)
            acc += __shfl_xor_sync(0xFFFFFFFFu, acc, off);
        G[e] = acc + gb[e];
    }

    if (lane == 0) {
        int e0 = 0;
        #pragma unroll
        for (int e = 1; e < NEXP; e++) if (G[e] > G[e0]) e0 = e;
        int e1 = (e0 == 0) ? 1 : 0;
        #pragma unroll
        for (int e = 0; e < NEXP; e++) if (e != e0 && G[e] > G[e1]) e1 = e;

        float v0 = G[e0], v1 = G[e1];
        float z1 = expf(v1 - v0);
        float s = 1.f + z1;
        float w0 = 1.f / s, w1 = z1 / s;

        int p0 = atomicAdd(&g_cnt[e0], 1);
        if (p0 < CAP) { g_tok[e0 * CAP + p0] = b * 2 + 0; g_wt[e0 * CAP + p0] = w0; }
        int p1 = atomicAdd(&g_cnt[e1], 1);
        if (p1 < CAP) { g_tok[e1 * CAP + p1] = b * 2 + 1; g_wt[e1 * CAP + p1] = w1; }
    }
}

// ---------------------------------------------------------------------------
// Kernel 2: grouped expert GEMM — mma.sync tf32x3 with pre-split (hi,lo)
// fragments fetched by single LDS.64. Dynamic smem, 2 CTAs/SM.
// ---------------------------------------------------------------------------
// Dynamic smem layout (bytes):
//   [0,512)       s_packed  int[128]
//   [512,1024)    s_wt      float[128]
//   [1024,1536)   s_tok     int[128]
//   [2048, +40960)  As[2][BM][SPAD] float2
//   [43008, +40960) Bs[2][BN][SPAD] float2
#define SM_AS   2048
#define SM_BS   (SM_AS + 2 * BM * SPAD * 8)
#define SM_GEMM (SM_BS + 2 * BN * SPAD * 8)      // 83968 B

__device__ __forceinline__ void load_tiles2(
    char* smem, int stage,
    const float2* __restrict__ a2, const float2* __restrict__ b2,
    const int* s_tok, int k0f2, int tid)
{
    float2 (*As)[SPAD] = reinterpret_cast<float2(*)[SPAD]>(smem + SM_AS + stage * BM * SPAD * 8);
    float2 (*Bs)[SPAD] = reinterpret_cast<float2(*)[SPAD]>(smem + SM_BS + stage * BN * SPAD * 8);
    #pragma unroll
    for (int it = 0; it < 4; it++) {
        int q   = tid + it * NTHREADS;     // 0..1023
        int row = q >> 3;
        int c   = (q & 7) * 2;             // float2 index, 16B granularity
        cp16(smem_u32(&As[row][c]), a2 + (size_t)s_tok[row] * HDIM + k0f2 + c);
        cp16(smem_u32(&Bs[row][c]), b2 + (size_t)row * HDIM + k0f2 + c);
    }
}

__global__ __launch_bounds__(NTHREADS, 2) void expert_gemm_kernel(
    int layer,
    const float* __restrict__ eb, const float* __restrict__ pl,
    const float* __restrict__ pr, const float* __restrict__ pp,
    const float* __restrict__ pb)
{
    int e      = blockIdx.z;
    int m_base = blockIdx.y * BM;
    int n_base = blockIdx.x * BN;

    int cnt = g_cnt[e];
    if (cnt > CAP) cnt = CAP;
    if (m_base >= cnt) return;

    extern __shared__ char smem[];
    int*   s_packed = reinterpret_cast<int*>(smem);
    float* s_wt     = reinterpret_cast<float*>(smem + 512);
    int*   s_tok    = reinterpret_cast<int*>(smem + 1024);

    int tid = threadIdx.x;
    if (tid < BM) {
        int slot = m_base + tid;
        int pk = 0; float wv = 0.f;
        if (slot < cnt) { pk = g_tok[e * CAP + slot]; wv = g_wt[e * CAP + slot]; }
        s_packed[tid] = pk; s_wt[tid] = wv; s_tok[tid] = pk >> 1;
    }
    __syncthreads();

    const float2* b2 = g_ew2 + ((size_t)layer * NEXP + e) * HDIM * HDIM + (size_t)n_base * HDIM;

    // Prologue: chunk 0 into stage 0
    load_tiles2(smem, 0, g_a2, b2, s_tok, 0, tid);
    cp_commit();

    int warp = tid >> 5;
    int lane = tid & 31;
    int wm   = (warp >> 2) * 64;
    int wn   = (warp & 3) * 32;
    int gid  = lane >> 2;
    int tg   = lane & 3;

    float acc[4][4][4];
    #pragma unroll
    for (int mi = 0; mi < 4; mi++)
        #pragma unroll
        for (int ni = 0; ni < 4; ni++)
            #pragma unroll
            for (int r = 0; r < 4; r++) acc[mi][ni][r] = 0.f;

    const int NCHUNK = HDIM / KC;   // 64
    for (int kc = 0; kc < NCHUNK; kc++) {
        int buf = kc & 1;
        if (kc + 1 < NCHUNK) {
            load_tiles2(smem, buf ^ 1, g_a2, b2, s_tok, (kc + 1) * KC, tid);
            cp_commit();
            cp_wait1();
        } else {
            cp_wait0();
        }
        __syncthreads();

        const float2 (*As)[SPAD] = reinterpret_cast<const float2(*)[SPAD]>(smem + SM_AS + buf * BM * SPAD * 8);
        const float2 (*Bs)[SPAD] = reinterpret_cast<const float2(*)[SPAD]>(smem + SM_BS + buf * BN * SPAD * 8);

        #pragma unroll
        for (int ks = 0; ks < 2; ks++) {
            int kb = ks * 8;
            // Each uint2 = (hi, lo) of one element — single LDS.64.
            uint2 aA[4][4], bB[4][2];
            #pragma unroll
            for (int mi = 0; mi < 4; mi++) {
                int r = wm + mi * 16 + gid;
                aA[mi][0] = *reinterpret_cast<const uint2*>(&As[r][kb + tg]);
                aA[mi][1] = *reinterpret_cast<const uint2*>(&As[r + 8][kb + tg]);
                aA[mi][2] = *reinterpret_cast<const uint2*>(&As[r][kb + tg + 4]);
                aA[mi][3] = *reinterpret_cast<const uint2*>(&As[r + 8][kb + tg + 4]);
            }
            #pragma unroll
            for (int ni = 0; ni < 4; ni++) {
                int cn = wn + ni * 8 + gid;
                bB[ni][0] = *reinterpret_cast<const uint2*>(&Bs[cn][kb + tg]);
                bB[ni][1] = *reinterpret_cast<const uint2*>(&Bs[cn][kb + tg + 4]);
            }
            // Three sweeps; dependent hits on one acc are 16 MMAs apart.
            #pragma unroll
            for (int mi = 0; mi < 4; mi++)
                #pragma unroll
                for (int ni = 0; ni < 4; ni++)
                    mma4(acc[mi][ni], aA[mi][0].x, aA[mi][1].x, aA[mi][2].x, aA[mi][3].x,
                         bB[ni][0].x, bB[ni][1].x);
            #pragma unroll
            for (int mi = 0; mi < 4; mi++)
                #pragma unroll
                for (int ni = 0; ni < 4; ni++)
                    mma4(acc[mi][ni], aA[mi][0].y, aA[mi][1].y, aA[mi][2].y, aA[mi][3].y,
                         bB[ni][0].x, bB[ni][1].x);
            #pragma unroll
            for (int mi = 0; mi < 4; mi++)
                #pragma unroll
                for (int ni = 0; ni < 4; ni++)
                    mma4(acc[mi][ni], aA[mi][0].x, aA[mi][1].x, aA[mi][2].x, aA[mi][3].x,
                         bB[ni][0].y, bB[ni][1].y);
        }
        __syncthreads();
    }

    // Epilogue: bias + PReLU + gate weight, scatter to pair buffer.
    const float* ebp = eb + (size_t)e * HDIM;
    const float* plp = pl + (size_t)e * HDIM;
    const float* prp = pr + (size_t)e * HDIM;
    const float* ppp = pp + (size_t)e * HDIM;
    const float* pbp = pb + (size_t)e * HDIM;

    #pragma unroll
    for (int ni = 0; ni < 4; ni++) {
        int o = n_base + wn + ni * 8 + 2 * tg;
        float2 e2 = *reinterpret_cast<const float2*>(ebp + o);
        float2 l2 = *reinterpret_cast<const float2*>(plp + o);
        float2 r2 = *reinterpret_cast<const float2*>(prp + o);
        float2 p2 = *reinterpret_cast<const float2*>(ppp + o);
        float2 b2e = *reinterpret_cast<const float2*>(pbp + o);
        #pragma unroll
        for (int mi = 0; mi < 4; mi++) {
            #pragma unroll
            for (int h = 0; h < 2; h++) {
                int r    = wm + mi * 16 + gid + h * 8;
                int slot = m_base + r;
                if (slot < cnt) {
                    int   packed = s_packed[r];
                    float w      = s_wt[r];
                    float y0 = acc[mi][ni][h * 2 + 0] + e2.x;
                    float d0 = y0 - p2.x;
                    float a0 = b2e.x + (d0 >= 0.f ? d0 * r2.x : d0 * l2.x);
                    float y1 = acc[mi][ni][h * 2 + 1] + e2.y;
                    float d1 = y1 - p2.y;
                    float a1 = b2e.y + (d1 >= 0.f ? d1 * r2.y : d1 * l2.y);
                    *reinterpret_cast<float2*>(&g_pair[(size_t)packed * HDIM + o]) =
                        make_float2(w * a0, w * a1);
                }
            }
        }
    }
}

// ---------------------------------------------------------------------------
// Kernel 3: combine the two weighted expert outputs per token (float4).
// ---------------------------------------------------------------------------
__global__ __launch_bounds__(256) void combine_kernel(int layer, float* __restrict__ out_ext) {
    float* dst = (layer == 0) ? g_act : out_ext;
    size_t i    = (size_t)blockIdx.x * blockDim.x + threadIdx.x;
    size_t elem = i * 4;
    size_t b    = elem >> 10;
    size_t o    = elem & (HDIM - 1);
    float4 p0 = *reinterpret_cast<const float4*>(&g_pair[b * 2 * HDIM + o]);
    float4 p1 = *reinterpret_cast<const float4*>(&g_pair[b * 2 * HDIM + HDIM + o]);
    float4 r  = make_float4(p0.x + p1.x, p0.y + p1.y, p0.z + p1.z, p0.w + p1.w);
    *reinterpret_cast<float4*>(&dst[elem]) = r;
}

// ---------------------------------------------------------------------------
// Launch
// ---------------------------------------------------------------------------
extern "C" void kernel_launch(void* const* d_in, const int* in_sizes, int n_in,
                              void* d_out, int out_size) {
    const float* X  = (const float*)d_in[0];
    const float* gw = (const float*)d_in[1];
    const float* gb = (const float*)d_in[2];
    const float* ew = (const float*)d_in[3];
    const float* eb = (const float*)d_in[4];
    const float* pl = (const float*)d_in[5];
    const float* pr = (const float*)d_in[6];
    const float* pp = (const float*)d_in[7];
    const float* pb = (const float*)d_in[8];
    float* out = (float*)d_out;

    cudaFuncSetAttribute(expert_gemm_kernel, cudaFuncAttributeMaxDynamicSharedMemorySize, SM_GEMM);

    // Split expert weights once (covers both layers)
    split_ew_kernel<<<(int)(((size_t)DEPTH * NEXP * HDIM * HDIM / 4) / 256), 256>>>(ew);

    for (int d = 0; d < DEPTH; d++) {
        const float* gw_d = gw + (size_t)d * NEXP * HDIM;
        const float* gb_d = gb + (size_t)d * NEXP;
        const float* eb_d = eb + (size_t)d * NEXP * HDIM;
        const float* pl_d = pl + (size_t)d * NEXP * HDIM;
        const float* pr_d = pr + (size_t)d * NEXP * HDIM;
        const float* pp_d = pp + (size_t)d * NEXP * HDIM;
        const float* pb_d = pb + (size_t)d * NEXP * HDIM;

        reset_kernel<<<1, 32>>>();
        gate_kernel<<<NTOK / 8, 256>>>(d, X, gw_d, gb_d);
        split_act_kernel<<<(NTOK * HDIM / 4) / 256, 256>>>(d, X);
        dim3 grid(HDIM / BN, CAP / BM, NEXP);   // (8, 32, 16); empty m-tiles exit fast
        expert_gemm_kernel<<<grid, NTHREADS, SM_GEMM>>>(d, eb_d, pl_d, pr_d, pp_d, pb_d);
        combine_kernel<<<(NTOK * HDIM / 4) / 256, 256>>>(d, out);
    }
}

// round 15
// speedup vs baseline: 1.2823x; 1.2823x over previous
#include <cuda_runtime.h>
#include <cstdint>

// Problem constants
#define DEPTH 2
#define NEXP  16
#define HDIM  1024
#define NTOK  8192
#define CAP   4096      // per-expert slot capacity (mean occupancy 1024)

// GEMM tile config
#define BM 128
#define BN 128
#define KC 32           // K floats per chunk (128B rows)
#define NTHREADS 256
#define LDS_PAD 36      // smem row stride in floats; bank=(4*gid+tg)%32 conflict-free

// ---------------------------------------------------------------------------
// Device-global scratch (no allocations allowed in kernel_launch)
// ---------------------------------------------------------------------------
__device__ float g_act[(size_t)NTOK * HDIM];          // layer-0 output activations
__device__ float g_pair[(size_t)NTOK * 2 * HDIM];     // per-assignment expert outputs
__device__ int   g_cnt[NEXP];
__device__ int   g_tok[NEXP * CAP];                   // packed token*2 + k
__device__ float g_wt[NEXP * CAP];                    // softmax gate weight per assignment

// ---------------------------------------------------------------------------
// Small PTX helpers
// ---------------------------------------------------------------------------
__device__ __forceinline__ uint32_t f2tf(float x) {
    uint32_t u;
    asm("cvt.rna.tf32.f32 %0, %1;" : "=r"(u) : "f"(x));
    return u;
}

// tf32x3 split: v = hi + lo (hi = rna.tf32(v); lo = rna.tf32(v - hi)).
__device__ __forceinline__ void f2tf_pair(float v, uint32_t& hi, uint32_t& lo) {
    hi = f2tf(v);
    lo = f2tf(v - __uint_as_float(hi));
}

__device__ __forceinline__ void mma_tf32(float* d, const uint32_t* a, const uint32_t* b) {
    asm volatile(
        "mma.sync.aligned.m16n8k8.row.col.f32.tf32.tf32.f32 "
        "{%0,%1,%2,%3}, {%4,%5,%6,%7}, {%8,%9}, {%0,%1,%2,%3};"
        : "+f"(d[0]), "+f"(d[1]), "+f"(d[2]), "+f"(d[3])
        : "r"(a[0]), "r"(a[1]), "r"(a[2]), "r"(a[3]), "r"(b[0]), "r"(b[1]));
}

__device__ __forceinline__ void cp16(uint32_t smem_dst, const void* gsrc) {
    asm volatile("cp.async.cg.shared.global [%0], [%1], 16;" :: "r"(smem_dst), "l"(gsrc));
}
__device__ __forceinline__ void cp_commit() { asm volatile("cp.async.commit_group;"); }
__device__ __forceinline__ void cp_wait1()  { asm volatile("cp.async.wait_group 1;"); }
__device__ __forceinline__ void cp_wait0()  { asm volatile("cp.async.wait_group 0;"); }

// ---------------------------------------------------------------------------
// Kernel 0: reset per-expert counters (per layer)
// ---------------------------------------------------------------------------
__global__ void reset_kernel() {
    if (threadIdx.x < NEXP) g_cnt[threadIdx.x] = 0;
}

// ---------------------------------------------------------------------------
// Kernel 1: gating — logits (fp32 FFMA), top-2, softmax, routing lists.
// ---------------------------------------------------------------------------
__global__ __launch_bounds__(256) void gate_kernel(
    int layer,
    const float* __restrict__ Xext,
    const float* __restrict__ gw,   // layer-offset: [NEXP, HDIM]
    const float* __restrict__ gb)   // layer-offset: [NEXP]
{
    const float* x = (layer == 0) ? Xext : g_act;

    __shared__ float4 sx4[8 * (HDIM / 4)];   // 8 tokens x 256 float4 = 32 KB

    int tid = threadIdx.x;
    const float4* x4 = reinterpret_cast<const float4*>(x);
    #pragma unroll
    for (int i = tid; i < 8 * (HDIM / 4); i += 256)
        sx4[i] = x4[(size_t)blockIdx.x * (8 * HDIM / 4) + i];
    __syncthreads();

    int wid  = tid >> 5;
    int lane = tid & 31;
    int b    = blockIdx.x * 8 + wid;

    const float4* gw4 = reinterpret_cast<const float4*>(gw);
    float G[NEXP];
    #pragma unroll
    for (int e = 0; e < NEXP; e++) {
        float acc = 0.f;
        #pragma unroll
        for (int j = 0; j < 8; j++) {
            float4 xv = sx4[wid * 256 + j * 32 + lane];
            float4 wv = gw4[e * 256 + j * 32 + lane];
            acc += xv.x * wv.x + xv.y * wv.y + xv.z * wv.z + xv.w * wv.w;
        }
        #pragma unroll
        for (int off = 16; off; off >>= 1)
            acc += __shfl_xor_sync(0xFFFFFFFFu, acc, off);
        G[e] = acc + gb[e];
    }

    if (lane == 0) {
        // top-2 with lowest-index tie-break (strict >), matching jax top_k
        int e0 = 0;
        #pragma unroll
        for (int e = 1; e < NEXP; e++) if (G[e] > G[e0]) e0 = e;
        int e1 = (e0 == 0) ? 1 : 0;
        #pragma unroll
        for (int e = 0; e < NEXP; e++) if (e != e0 && G[e] > G[e1]) e1 = e;

        float v0 = G[e0], v1 = G[e1];
        float z1 = expf(v1 - v0);          // v0 >= v1 -> stable
        float s  = 1.f + z1;
        float w0 = 1.f / s;
        float w1 = z1 / s;

        int p0 = atomicAdd(&g_cnt[e0], 1);
        if (p0 < CAP) { g_tok[e0 * CAP + p0] = b * 2 + 0; g_wt[e0 * CAP + p0] = w0; }
        int p1 = atomicAdd(&g_cnt[e1], 1);
        if (p1 < CAP) { g_tok[e1 * CAP + p1] = b * 2 + 1; g_wt[e1 * CAP + p1] = w1; }
    }
}

// ---------------------------------------------------------------------------
// Kernel 2: grouped expert GEMM (tf32x3 / tf32x2 mma.sync)
//           + bias + PReLU + gate weight epilogue.
// sweeps3=1: hi*hi + lo*hi + hi*lo (fp32-grade; layer feeding routing)
// sweeps3=0: hi*hi + lo*hi          (~2.4e-4 rel; final layer)
// ---------------------------------------------------------------------------
__device__ __forceinline__ void load_tiles(
    const float* __restrict__ xin, const float* __restrict__ W,
    const int* s_tok, float (*As)[LDS_PAD], float (*Bs)[LDS_PAD],
    int n_base, int k0, int tid)
{
    #pragma unroll
    for (int it = 0; it < 4; it++) {
        int q   = tid + it * 256;          // 0..1023
        int row = q >> 3;                  // 0..127
        int cc  = (q & 7) * 4;             // 0..28
        const float* asrc = xin + (size_t)(s_tok[row] >> 1) * HDIM + k0 + cc;
        cp16((uint32_t)__cvta_generic_to_shared(&As[row][cc]), asrc);
        const float* bsrc = W + (size_t)(n_base + row) * HDIM + k0 + cc;
        cp16((uint32_t)__cvta_generic_to_shared(&Bs[row][cc]), bsrc);
    }
}

__global__ __launch_bounds__(NTHREADS, 1) void expert_gemm_kernel(
    int layer, int sweeps3,
    const float* __restrict__ Xext,
    const float* __restrict__ ew,   // layer-offset: [NEXP, HDIM, HDIM] (o,i)
    const float* __restrict__ eb,   // layer-offset: [NEXP, HDIM]
    const float* __restrict__ pl,
    const float* __restrict__ pr,
    const float* __restrict__ pp,
    const float* __restrict__ pb)
{
    int e      = blockIdx.z;
    int m_base = blockIdx.y * BM;
    int n_base = blockIdx.x * BN;

    int cnt = g_cnt[e];
    if (cnt > CAP) cnt = CAP;
    if (m_base >= cnt) return;

    const float* xin = (layer == 0) ? Xext : g_act;
    const float* W   = ew + (size_t)e * HDIM * HDIM;

    __shared__ float As[2][BM][LDS_PAD];
    __shared__ float Bs[2][BN][LDS_PAD];
    __shared__ int   s_tok[BM];
    __shared__ float s_wt[BM];

    int tid = threadIdx.x;
    if (tid < BM) {
        s_tok[tid] = g_tok[e * CAP + m_base + tid];
        s_wt[tid]  = g_wt[e * CAP + m_base + tid];
    }
    __syncthreads();

    // Prologue: chunk 0 into buffer 0
    load_tiles(xin, W, s_tok, As[0], Bs[0], n_base, 0, tid);
    cp_commit();

    int warp = tid >> 5;
    int lane = tid & 31;
    int wm   = (warp >> 2) * 64;   // warp row offset (2 warp-rows)
    int wn   = (warp & 3) * 32;    // warp col offset (4 warp-cols)
    int gid  = lane >> 2;
    int tg   = lane & 3;

    float acc[4][4][4];
    #pragma unroll
    for (int mi = 0; mi < 4; mi++)
        #pragma unroll
        for (int ni = 0; ni < 4; ni++)
            #pragma unroll
            for (int r = 0; r < 4; r++) acc[mi][ni][r] = 0.f;

    const int NCHUNK = HDIM / KC;   // 32
    for (int kc = 0; kc < NCHUNK; kc++) {
        int buf = kc & 1;
        if (kc + 1 < NCHUNK) {
            load_tiles(xin, W, s_tok, As[buf ^ 1], Bs[buf ^ 1], n_base, (kc + 1) * KC, tid);
            cp_commit();
            cp_wait1();
        } else {
            cp_wait0();
        }
        __syncthreads();

        #pragma unroll
        for (int ks = 0; ks < 4; ks++) {
            int kb = ks * 8;
            // tf32x3 fragments: hi and lo halves of A and B
            uint32_t afh[4][4], afl[4][4], bfh[4][2], bfl[4][2];
            #pragma unroll
            for (int mi = 0; mi < 4; mi++) {
                int r = wm + mi * 16 + gid;
                f2tf_pair(As[buf][r][kb + tg],         afh[mi][0], afl[mi][0]);
                f2tf_pair(As[buf][r + 8][kb + tg],     afh[mi][1], afl[mi][1]);
                f2tf_pair(As[buf][r][kb + tg + 4],     afh[mi][2], afl[mi][2]);
                f2tf_pair(As[buf][r + 8][kb + tg + 4], afh[mi][3], afl[mi][3]);
            }
            #pragma unroll
            for (int ni = 0; ni < 4; ni++) {
                int cn = wn + ni * 8 + gid;
                f2tf_pair(Bs[buf][cn][kb + tg],     bfh[ni][0], bfl[ni][0]);
                f2tf_pair(Bs[buf][cn][kb + tg + 4], bfh[ni][1], bfl[ni][1]);
            }
            // Sweeps; dependent hits on one acc are 16 independent MMAs apart.
            #pragma unroll
            for (int mi = 0; mi < 4; mi++)
                #pragma unroll
                for (int ni = 0; ni < 4; ni++)
                    mma_tf32(acc[mi][ni], afh[mi], bfh[ni]);
            #pragma unroll
            for (int mi = 0; mi < 4; mi++)
                #pragma unroll
                for (int ni = 0; ni < 4; ni++)
                    mma_tf32(acc[mi][ni], afl[mi], bfh[ni]);
            if (sweeps3) {
                #pragma unroll
                for (int mi = 0; mi < 4; mi++)
                    #pragma unroll
                    for (int ni = 0; ni < 4; ni++)
                        mma_tf32(acc[mi][ni], afh[mi], bfl[ni]);
            }
        }
        __syncthreads();
    }

    // Epilogue: bias + PReLU + gate weight, scatter to pair buffer.
    const float* ebp = eb + (size_t)e * HDIM;
    const float* plp = pl + (size_t)e * HDIM;
    const float* prp = pr + (size_t)e * HDIM;
    const float* ppp = pp + (size_t)e * HDIM;
    const float* pbp = pb + (size_t)e * HDIM;

    #pragma unroll
    for (int ni = 0; ni < 4; ni++) {
        int o = n_base + wn + ni * 8 + 2 * tg;
        float2 e2 = *reinterpret_cast<const float2*>(ebp + o);
        float2 l2 = *reinterpret_cast<const float2*>(plp + o);
        float2 r2 = *reinterpret_cast<const float2*>(prp + o);
        float2 p2 = *reinterpret_cast<const float2*>(ppp + o);
        float2 b2 = *reinterpret_cast<const float2*>(pbp + o);
        #pragma unroll
        for (int mi = 0; mi < 4; mi++) {
            #pragma unroll
            for (int h = 0; h < 2; h++) {
                int r    = wm + mi * 16 + gid + h * 8;
                int slot = m_base + r;
                if (slot < cnt) {
                    int   packed = s_tok[r];
                    float w      = s_wt[r];
                    float y0 = acc[mi][ni][h * 2 + 0] + e2.x;
                    float d0 = y0 - p2.x;
                    float a0 = b2.x + (d0 >= 0.f ? d0 * r2.x : d0 * l2.x);
                    float y1 = acc[mi][ni][h * 2 + 1] + e2.y;
                    float d1 = y1 - p2.y;
                    float a1 = b2.y + (d1 >= 0.f ? d1 * r2.y : d1 * l2.y);
                    float2 out2 = make_float2(w * a0, w * a1);
                    *reinterpret_cast<float2*>(&g_pair[(size_t)packed * HDIM + o]) = out2;
                }
            }
        }
    }
}

// ---------------------------------------------------------------------------
// Kernel 3: combine the two weighted expert outputs per token (float4).
// ---------------------------------------------------------------------------
__global__ __launch_bounds__(256) void combine_kernel(int layer, float* __restrict__ out_ext) {
    float* dst = (layer == 0) ? g_act : out_ext;
    size_t i    = (size_t)blockIdx.x * blockDim.x + threadIdx.x;  // over B*H/4
    size_t elem = i * 4;
    size_t b    = elem >> 10;          // / HDIM
    size_t o    = elem & (HDIM - 1);
    float4 p0 = *reinterpret_cast<const float4*>(&g_pair[b * 2 * HDIM + o]);
    float4 p1 = *reinterpret_cast<const float4*>(&g_pair[b * 2 * HDIM + HDIM + o]);
    float4 r  = make_float4(p0.x + p1.x, p0.y + p1.y, p0.z + p1.z, p0.w + p1.w);
    *reinterpret_cast<float4*>(&dst[elem]) = r;
}

// ---------------------------------------------------------------------------
// Launch
// ---------------------------------------------------------------------------
extern "C" void kernel_launch(void* const* d_in, const int* in_sizes, int n_in,
                              void* d_out, int out_size) {
    const float* X  = (const float*)d_in[0];
    const float* gw = (const float*)d_in[1];
    const float* gb = (const float*)d_in[2];
    const float* ew = (const float*)d_in[3];
    const float* eb = (const float*)d_in[4];
    const float* pl = (const float*)d_in[5];
    const float* pr = (const float*)d_in[6];
    const float* pp = (const float*)d_in[7];
    const float* pb = (const float*)d_in[8];
    float* out = (float*)d_out;

    for (int d = 0; d < DEPTH; d++) {
        const float* gw_d = gw + (size_t)d * NEXP * HDIM;
        const float* gb_d = gb + (size_t)d * NEXP;
        const float* ew_d = ew + (size_t)d * NEXP * HDIM * HDIM;
        const float* eb_d = eb + (size_t)d * NEXP * HDIM;
        const float* pl_d = pl + (size_t)d * NEXP * HDIM;
        const float* pr_d = pr + (size_t)d * NEXP * HDIM;
        const float* pp_d = pp + (size_t)d * NEXP * HDIM;
        const float* pb_d = pb + (size_t)d * NEXP * HDIM;

        int sweeps3 = (d == 0) ? 1 : 0;   // layer 0 feeds routing: full tf32x3;
                                          // final layer: tf32x2 (~2.4e-4 rel, safe)
        reset_kernel<<<1, 32>>>();
        gate_kernel<<<NTOK / 8, 256>>>(d, X, gw_d, gb_d);
        dim3 grid(HDIM / BN, CAP / BM, NEXP);   // (8, 32, 16); empty m-tiles exit fast
        expert_gemm_kernel<<<grid, NTHREADS>>>(d, sweeps3, X, ew_d, eb_d,
                                               pl_d, pr_d, pp_d, pb_d);
        combine_kernel<<<(NTOK * HDIM / 4) / 256, 256>>>(d, out);
    }
}